// round 13
// baseline (speedup 1.0000x reference)
#include <cuda_runtime.h>
#include <cuda_fp16.h>
#include <cstdint>

// Problem constants
#define BATCH 2
#define SEQ   2048
#define DIM   1024
#define HEADS 16
#define DHEAD 64
#define NQT   (SEQ / 128)          // 16 q-tiles

typedef __half f16;

// Scratch (device globals — no allocations allowed)
__device__ f16 g_xh [(size_t)BATCH * SEQ * DIM];
__device__ f16 g_wih[(size_t)3 * DIM * DIM];
__device__ f16 g_woh[(size_t)DIM * DIM];
__device__ f16 g_qkvh[(size_t)BATCH * SEQ * 3 * DIM];
__device__ f16 g_ah [(size_t)BATCH * SEQ * DIM];

// ---------------------------------------------------------------------------
// helpers
// ---------------------------------------------------------------------------
__device__ __forceinline__ uint32_t smem_u32(const void* p) {
    uint32_t a;
    asm("{ .reg .u64 t; cvta.to.shared.u64 t, %1; cvt.u32.u64 %0, t; }" : "=r"(a) : "l"(p));
    return a;
}

__device__ __forceinline__ void ldmatrix_x4(uint32_t* r, uint32_t addr) {
    asm volatile("ldmatrix.sync.aligned.m8n8.x4.shared.b16 {%0,%1,%2,%3}, [%4];"
                 : "=r"(r[0]), "=r"(r[1]), "=r"(r[2]), "=r"(r[3]) : "r"(addr));
}

__device__ __forceinline__ void ldmatrix_x4_trans(uint32_t* r, uint32_t addr) {
    asm volatile("ldmatrix.sync.aligned.m8n8.x4.trans.shared.b16 {%0,%1,%2,%3}, [%4];"
                 : "=r"(r[0]), "=r"(r[1]), "=r"(r[2]), "=r"(r[3]) : "r"(addr));
}

__device__ __forceinline__ void mma_f16(float* c, const uint32_t* a, const uint32_t* b) {
    asm volatile(
        "mma.sync.aligned.m16n8k16.row.col.f32.f16.f16.f32 "
        "{%0,%1,%2,%3}, {%4,%5,%6,%7}, {%8,%9}, {%0,%1,%2,%3};"
        : "+f"(c[0]), "+f"(c[1]), "+f"(c[2]), "+f"(c[3])
        : "r"(a[0]), "r"(a[1]), "r"(a[2]), "r"(a[3]), "r"(b[0]), "r"(b[1]));
}

__device__ __forceinline__ uint32_t pack_f16(float a, float b) {
    __half2 t = __floats2half2_rn(a, b);
    return *(uint32_t*)&t;
}

__device__ __forceinline__ void cp16(uint32_t dst, const void* src) {
    asm volatile("cp.async.cg.shared.global [%0], [%1], 16;" :: "r"(dst), "l"(src));
}
#define CP_COMMIT() asm volatile("cp.async.commit_group;" ::: "memory")
#define CP_WAIT1()  asm volatile("cp.async.wait_group 1;" ::: "memory")
#define CP_WAIT0()  asm volatile("cp.async.wait_group 0;" ::: "memory")

// ---------------------------------------------------------------------------
// fused fp32 -> fp16 conversion (hi only)
// ---------------------------------------------------------------------------
#define N4X (BATCH * SEQ * DIM / 4)      // 1048576
#define N4W (3 * DIM * DIM / 4)          // 786432
#define N4O (DIM * DIM / 4)              // 262144

__global__ void cvt_all(const float4* __restrict__ x,
                        const float4* __restrict__ w_in,
                        const float4* __restrict__ w_out,
                        uint2* __restrict__ xh, uint2* __restrict__ wih,
                        uint2* __restrict__ woh)
{
    int i = blockIdx.x * blockDim.x + threadIdx.x;
    if (i < N4X) {
        float4 f = x[i];
        xh[i] = make_uint2(pack_f16(f.x, f.y), pack_f16(f.z, f.w));
    }
    if (i < N4W) {
        float4 f = w_in[i];
        wih[i] = make_uint2(pack_f16(f.x, f.y), pack_f16(f.z, f.w));
    }
    if (i < N4O) {
        float4 f = w_out[i];
        woh[i] = make_uint2(pack_f16(f.x, f.y), pack_f16(f.z, f.w));
    }
}

// ---------------------------------------------------------------------------
// GEMM: 128x128 tile, pure fp16 (C = Ah*Bh + bias), 256 threads, 2 CTAs/SM.
// BK=64 (16 barriers instead of 32), 3-stage cp.async ring.
// Stage = [A 128x144B | B 128x144B] = 36864 B; 3 stages = 110592 B.
// Rows padded to 144B: (r+chunk) mod 8 permutation -> conflict-free ldmatrix.
// OUTHALF=1: fp16 out, columns < qcols scaled 0.125. OUTHALF=0: fp32 out.
// ---------------------------------------------------------------------------
#define GSTR  144
#define GTILE 18432               // 128 * 144
#define GSTG  (2 * GTILE)         // 36864
#define GEMM_SMEM (3 * GSTG)      // 110592

template <int OUTHALF>
__global__ __launch_bounds__(256, 2)
void gemm_k(int M, int N, int K,
            const f16* __restrict__ Ah, const f16* __restrict__ Bh,
            const float* __restrict__ bias, int qcols,
            float* __restrict__ C, f16* __restrict__ Ch)
{
    extern __shared__ char smem[];
    const uint32_t sb = smem_u32(smem);
    const int tid = threadIdx.x, wid = tid >> 5, lane = tid & 31;
    const int bx = blockIdx.x, by = blockIdx.y;
    const int warpM = wid & 1, warpN = wid >> 1;

    // cp.async mapping: row r, half-row of 64B = 4 x 16B chunks
    const int r = tid >> 1;
    const int ch = tid & 1;
    const f16* pAh = Ah + (size_t)(by * 128 + r) * K;
    const f16* pBh = Bh + (size_t)(bx * 128 + r) * K;
    const uint32_t sdst = sb + (uint32_t)(r * GSTR + ch * 64);

    float acc[4][4][4];
#pragma unroll
    for (int i = 0; i < 4; i++)
#pragma unroll
        for (int j = 0; j < 4; j++)
#pragma unroll
            for (int v = 0; v < 4; v++) acc[i][j][v] = 0.f;

    const int KC = K >> 6;   // 16 chunks of 64

    auto issue = [&](int kt, int s) {
        const int k0 = kt * 64 + ch * 32;
        const uint32_t d = sdst + (uint32_t)(s * GSTG);
#pragma unroll
        for (int j = 0; j < 4; j++) {
            cp16(d + j * 16,         pAh + k0 + j * 8);
            cp16(d + GTILE + j * 16, pBh + k0 + j * 8);
        }
        CP_COMMIT();
    };

    issue(0, 0);
    issue(1, 1);

    const int aRow = warpM * 64 + ((lane >> 3) & 1) * 8 + (lane & 7);
    const int aColHalf = (lane >> 4) * 16;
    const int bRow = warpN * 32 + (lane >> 4) * 8 + (lane & 7);
    const int bColHalf = ((lane >> 3) & 1) * 16;

    for (int kt = 0; kt < KC; kt++) {
        CP_WAIT1();
        __syncthreads();
        if (kt + 2 < KC) issue(kt + 2, (kt + 2) % 3);
        else             CP_COMMIT();

        const uint32_t sAh = sb + (uint32_t)((kt % 3) * GSTG);
        const uint32_t sBh = sAh + GTILE;

#pragma unroll
        for (int ks = 0; ks < 4; ks++) {
            uint32_t ah[4][4], bh[4][2];
            const uint32_t acol = (uint32_t)(ks * 32 + aColHalf);
            const uint32_t bcol = (uint32_t)(ks * 32 + bColHalf);
#pragma unroll
            for (int mt = 0; mt < 4; mt++) {
                uint32_t off = (uint32_t)((aRow + mt * 16) * GSTR) + acol;
                ldmatrix_x4(ah[mt], sAh + off);
            }
#pragma unroll
            for (int pr = 0; pr < 2; pr++) {
                uint32_t off = (uint32_t)((bRow + pr * 16) * GSTR) + bcol;
                uint32_t r0[4];
                ldmatrix_x4(r0, sBh + off);
                bh[pr * 2 + 0][0] = r0[0]; bh[pr * 2 + 0][1] = r0[1];
                bh[pr * 2 + 1][0] = r0[2]; bh[pr * 2 + 1][1] = r0[3];
            }
#pragma unroll
            for (int mt = 0; mt < 4; mt++)
#pragma unroll
                for (int nt = 0; nt < 4; nt++)
                    mma_f16(acc[mt][nt], ah[mt], bh[nt]);
        }
    }

    const int crow = by * 128 + warpM * 64 + (lane >> 2);
    const int ccol = bx * 128 + warpN * 32 + (lane & 3) * 2;
#pragma unroll
    for (int nt = 0; nt < 4; nt++) {
        const int col = ccol + nt * 8;
        const float s = (OUTHALF && col < qcols) ? 0.125f : 1.0f;
        const float b0 = bias[col], b1 = bias[col + 1];
#pragma unroll
        for (int mt = 0; mt < 4; mt++) {
            const int r0 = crow + mt * 16;
            const float v00 = (acc[mt][nt][0] + b0) * s, v01 = (acc[mt][nt][1] + b1) * s;
            const float v10 = (acc[mt][nt][2] + b0) * s, v11 = (acc[mt][nt][3] + b1) * s;
            if (OUTHALF) {
                *(uint32_t*)(Ch + (size_t)r0 * N + col)       = pack_f16(v00, v01);
                *(uint32_t*)(Ch + (size_t)(r0 + 8) * N + col) = pack_f16(v10, v11);
            } else {
                *(float2*)(C + (size_t)r0 * N + col)       = make_float2(v00, v01);
                *(float2*)(C + (size_t)(r0 + 8) * N + col) = make_float2(v10, v11);
            }
        }
    }
}

// ---------------------------------------------------------------------------
// Flash attention, pure fp16, causal, WORK-PAIRED: CTA bi handles q-tiles
// {bi, NQT-1-bi} -> constant 34 KV-tile loads per CTA -> one uniform wave.
// Grid: (NQT/2, B*H), 256 threads, 2 CTAs/SM. 3-stage cp.async.
// Stage (18432B) = [Kh 9216 | Vh 9216], rows padded to 144B.
// ---------------------------------------------------------------------------
#define ASTR 144
#define KV_T 9216
#define STG_A 18432
#define ATT_SMEM (3 * STG_A)       // 55296

__global__ __launch_bounds__(256, 2)
void attn_mma(const f16* __restrict__ qkvh, f16* __restrict__ oh,
              const int* __restrict__ maskp)
{
    extern __shared__ char sm[];
    const uint32_t sb = smem_u32(sm);
    const int tid = threadIdx.x, wid = tid >> 5, lane = tid & 31;
    const int bi = blockIdx.x;
    const int bh = blockIdx.y;
    const int b = bh >> 4, h = bh & 15;
    const int mask = maskp[0];

    // constant per-thread addressing
    const int tt = tid & 127;
    const int kr = tt >> 1, kc0 = (tt & 1) * 4;
    const size_t kvcol = h * 64 + (tid < 128 ? DIM : 2 * DIM) + kc0 * 8;
    const uint32_t kvdst = (uint32_t)((tid < 128 ? 0 : KV_T) + kr * ASTR + kc0 * 16);
    const uint32_t koff = (uint32_t)(
        (((lane >> 4) << 3) + (lane & 7)) * ASTR + (((lane >> 3) & 1) * 8) * 2);
    const uint32_t voff = (uint32_t)(KV_T +
        ((((lane >> 3) & 1) * 8 + (lane & 7)) * ASTR) + (((lane >> 4) & 1) * 8) * 2);

#pragma unroll 1
    for (int p = 0; p < 2; p++) {
        const int qt = p ? (NQT - 1 - bi) : bi;
        const int q0 = qt * 128;

        // ---- stage Qh via cp.async, consume into registers ----
        {
            const int r = tid >> 1, c0 = (tid & 1) * 4;
            const size_t grow = ((size_t)(b * SEQ + q0 + r)) * (3 * DIM) + h * 64 + c0 * 8;
            const uint32_t dh = sb + (uint32_t)(r * ASTR + c0 * 16);
#pragma unroll
            for (int j = 0; j < 4; j++)
                cp16(dh + j * 16, qkvh + grow + j * 8);
            CP_COMMIT();
            CP_WAIT0();
            __syncthreads();
        }

        uint32_t qh[4][4];
#pragma unroll
        for (int j = 0; j < 4; j++) {
            uint32_t addr = sb + (uint32_t)((wid * 16 + (lane & 15)) * ASTR
                           + (j * 16 + ((lane >> 4) & 1) * 8) * 2);
            ldmatrix_x4(qh[j], addr);
        }
        __syncthreads();

        float o[8][4];
#pragma unroll
        for (int t = 0; t < 8; t++)
#pragma unroll
            for (int v = 0; v < 4; v++) o[t][v] = 0.f;
        float m0 = -1e30f, m1 = -1e30f, l0 = 0.f, l1 = 0.f;

        const int nkt_load = mask ? (2 * qt + 2) : (SEQ / 64);
        const int nkt_w    = mask ? (2 * qt + 1 + (wid >= 4 ? 1 : 0)) : (SEQ / 64);

        auto issueKV = [&](int kt, int s) {
            const size_t grow = ((size_t)(b * SEQ + kt * 64 + kr)) * (3 * DIM) + kvcol;
            const uint32_t d = sb + (uint32_t)(s * STG_A) + kvdst;
#pragma unroll
            for (int j = 0; j < 4; j++)
                cp16(d + j * 16, qkvh + grow + j * 8);
            CP_COMMIT();
        };

        issueKV(0, 0);
        if (nkt_load > 1) issueKV(1, 1); else CP_COMMIT();

        for (int kt = 0; kt < nkt_load; kt++) {
            CP_WAIT1();
            __syncthreads();
            if (kt + 2 < nkt_load) issueKV(kt + 2, (kt + 2) % 3);
            else                   CP_COMMIT();
            if (kt >= nkt_w) continue;

            const uint32_t stg = sb + (uint32_t)((kt % 3) * STG_A);
            const uint32_t kfrag = stg + koff;
            const uint32_t vfrag = stg + voff;

            // ---- scores = Qs * Kh ----
            float sc[8][4];
#pragma unroll
            for (int t = 0; t < 8; t++)
#pragma unroll
                for (int v = 0; v < 4; v++) sc[t][v] = 0.f;

#pragma unroll
            for (int j = 0; j < 4; j++) {
#pragma unroll
                for (int t = 0; t < 4; t++) {
                    uint32_t addr = kfrag + (uint32_t)(t * 16 * ASTR + j * 32);
                    uint32_t rh[4];
                    ldmatrix_x4(rh, addr);
                    mma_f16(sc[2 * t + 0], qh[j], rh);
                    mma_f16(sc[2 * t + 1], qh[j], rh + 2);
                }
            }

            // ---- online softmax ----
            const int row0 = q0 + wid * 16 + (lane >> 2);
            const int row1 = row0 + 8;
            const int cbase = kt * 64 + (lane & 3) * 2;
            const bool needmask = mask && (kt * 64 + 63 > q0 + wid * 16);
            if (needmask) {
#pragma unroll
                for (int t = 0; t < 8; t++) {
                    int c0 = cbase + t * 8, c1 = c0 + 1;
                    if (c0 > row0) sc[t][0] = -1e30f;
                    if (c1 > row0) sc[t][1] = -1e30f;
                    if (c0 > row1) sc[t][2] = -1e30f;
                    if (c1 > row1) sc[t][3] = -1e30f;
                }
            }
            float mt0 = -1e30f, mt1 = -1e30f;
#pragma unroll
            for (int t = 0; t < 8; t++) {
                mt0 = fmaxf(mt0, fmaxf(sc[t][0], sc[t][1]));
                mt1 = fmaxf(mt1, fmaxf(sc[t][2], sc[t][3]));
            }
            mt0 = fmaxf(mt0, __shfl_xor_sync(0xffffffffu, mt0, 1));
            mt0 = fmaxf(mt0, __shfl_xor_sync(0xffffffffu, mt0, 2));
            mt1 = fmaxf(mt1, __shfl_xor_sync(0xffffffffu, mt1, 1));
            mt1 = fmaxf(mt1, __shfl_xor_sync(0xffffffffu, mt1, 2));
            const float mn0 = fmaxf(m0, mt0), mn1 = fmaxf(m1, mt1);
            const float a0 = __expf(m0 - mn0), a1 = __expf(m1 - mn1);

            uint32_t ph[8][2];
            float s0 = 0.f, s1 = 0.f;
#pragma unroll
            for (int t = 0; t < 8; t++) {
                float p00 = __expf(sc[t][0] - mn0);
                float p01 = __expf(sc[t][1] - mn0);
                float p10 = __expf(sc[t][2] - mn1);
                float p11 = __expf(sc[t][3] - mn1);
                s0 += p00 + p01;
                s1 += p10 + p11;
                ph[t][0] = pack_f16(p00, p01);
                ph[t][1] = pack_f16(p10, p11);
            }
            s0 += __shfl_xor_sync(0xffffffffu, s0, 1);
            s0 += __shfl_xor_sync(0xffffffffu, s0, 2);
            s1 += __shfl_xor_sync(0xffffffffu, s1, 1);
            s1 += __shfl_xor_sync(0xffffffffu, s1, 2);
            m0 = mn0; m1 = mn1;
            l0 = l0 * a0 + s0;
            l1 = l1 * a1 + s1;
#pragma unroll
            for (int t = 0; t < 8; t++) {
                o[t][0] *= a0; o[t][1] *= a0;
                o[t][2] *= a1; o[t][3] *= a1;
            }

            // ---- O += Ph * Vh ----
#pragma unroll
            for (int j = 0; j < 4; j++) {
                uint32_t afh[4] = { ph[2*j][0], ph[2*j][1], ph[2*j+1][0], ph[2*j+1][1] };
#pragma unroll
                for (int t = 0; t < 4; t++) {
                    uint32_t addr = vfrag + (uint32_t)(j * 16 * ASTR + t * 32);
                    uint32_t rh[4];
                    ldmatrix_x4_trans(rh, addr);
                    mma_f16(o[2 * t + 0], afh, rh);
                    mma_f16(o[2 * t + 1], afh, rh + 2);
                }
            }
        }

        // ---- write O (fp16 — feeds proj as A operand) ----
        const float il0 = 1.0f / l0, il1 = 1.0f / l1;
        const int orow = q0 + wid * 16 + (lane >> 2);
        const size_t obase = ((size_t)b * SEQ + orow) * DIM + h * 64 + (lane & 3) * 2;
#pragma unroll
        for (int t = 0; t < 8; t++) {
            *(uint32_t*)(oh + obase + t * 8)           = pack_f16(o[t][0] * il0, o[t][1] * il0);
            *(uint32_t*)(oh + obase + 8 * DIM + t * 8) = pack_f16(o[t][2] * il1, o[t][3] * il1);
        }

        // drain outstanding cp.async before reusing smem for next sub-tile
        CP_WAIT0();
        __syncthreads();
    }
}

// ---------------------------------------------------------------------------
// Launch
// ---------------------------------------------------------------------------
extern "C" void kernel_launch(void* const* d_in, const int* in_sizes, int n_in,
                              void* d_out, int out_size)
{
    const float* x     = (const float*)d_in[0];
    const float* w_in  = (const float*)d_in[1];
    const float* b_in  = (const float*)d_in[2];
    const float* w_out = (const float*)d_in[3];
    const float* b_out = (const float*)d_in[4];
    const int*   mask  = (const int*)d_in[5];
    float* out = (float*)d_out;

    f16 *xh, *wih, *woh, *qkvh, *ah;
    cudaGetSymbolAddress((void**)&xh,  g_xh);
    cudaGetSymbolAddress((void**)&wih, g_wih);
    cudaGetSymbolAddress((void**)&woh, g_woh);
    cudaGetSymbolAddress((void**)&qkvh, g_qkvh);
    cudaGetSymbolAddress((void**)&ah,  g_ah);

    const int M = BATCH * SEQ;      // 4096
    const int K = DIM;              // 1024
    const int N1 = 3 * DIM;         // 3072
    const int N2 = DIM;             // 1024

    cudaFuncSetAttribute((const void*)gemm_k<1>, cudaFuncAttributeMaxDynamicSharedMemorySize, GEMM_SMEM);
    cudaFuncSetAttribute((const void*)gemm_k<0>, cudaFuncAttributeMaxDynamicSharedMemorySize, GEMM_SMEM);
    cudaFuncSetAttribute(attn_mma, cudaFuncAttributeMaxDynamicSharedMemorySize, ATT_SMEM);

    // 0) fused conversion (x, w_in, w_out -> fp16)
    cvt_all<<<(N4X + 255) / 256, 256>>>((const float4*)x, (const float4*)w_in,
                                        (const float4*)w_out,
                                        (uint2*)xh, (uint2*)wih, (uint2*)woh);
    // 1) QKV projection (pure fp16, BK=64) -> fp16, Q columns pre-scaled 0.125
    {
        dim3 grid(N1 / 128, M / 128);
        gemm_k<1><<<grid, 256, GEMM_SMEM>>>(M, N1, K, xh, wih, b_in, DIM,
                                            nullptr, qkvh);
    }
    // 2) causal attention (work-paired) -> fp16
    {
        dim3 grid(NQT / 2, BATCH * HEADS);
        attn_mma<<<grid, 256, ATT_SMEM>>>(qkvh, ah, mask);
    }
    // 3) output projection (pure fp16, BK=64) -> fp32 out
    {
        dim3 grid(N2 / 128, M / 128);
        gemm_k<0><<<grid, 256, GEMM_SMEM>>>(M, N2, K, ah, woh, b_out, 0,
                                            out, nullptr);
    }
}

// round 14
// speedup vs baseline: 1.0643x; 1.0643x over previous
#include <cuda_runtime.h>
#include <cuda_fp16.h>
#include <cstdint>

// Problem constants
#define BATCH 2
#define SEQ   2048
#define DIM   1024
#define HEADS 16
#define DHEAD 64
#define NQT   (SEQ / 128)          // 16 q-tiles

typedef __half f16;

// Scratch (device globals — no allocations allowed)
__device__ f16 g_xh [(size_t)BATCH * SEQ * DIM];
__device__ f16 g_wih[(size_t)3 * DIM * DIM];
__device__ f16 g_woh[(size_t)DIM * DIM];
__device__ f16 g_qkvh[(size_t)BATCH * SEQ * 3 * DIM];
__device__ f16 g_ah [(size_t)BATCH * SEQ * DIM];

// ---------------------------------------------------------------------------
// helpers
// ---------------------------------------------------------------------------
__device__ __forceinline__ uint32_t smem_u32(const void* p) {
    uint32_t a;
    asm("{ .reg .u64 t; cvta.to.shared.u64 t, %1; cvt.u32.u64 %0, t; }" : "=r"(a) : "l"(p));
    return a;
}

__device__ __forceinline__ void ldmatrix_x4(uint32_t* r, uint32_t addr) {
    asm volatile("ldmatrix.sync.aligned.m8n8.x4.shared.b16 {%0,%1,%2,%3}, [%4];"
                 : "=r"(r[0]), "=r"(r[1]), "=r"(r[2]), "=r"(r[3]) : "r"(addr));
}

__device__ __forceinline__ void ldmatrix_x4_trans(uint32_t* r, uint32_t addr) {
    asm volatile("ldmatrix.sync.aligned.m8n8.x4.trans.shared.b16 {%0,%1,%2,%3}, [%4];"
                 : "=r"(r[0]), "=r"(r[1]), "=r"(r[2]), "=r"(r[3]) : "r"(addr));
}

__device__ __forceinline__ void mma_f16(float* c, const uint32_t* a, const uint32_t* b) {
    asm volatile(
        "mma.sync.aligned.m16n8k16.row.col.f32.f16.f16.f32 "
        "{%0,%1,%2,%3}, {%4,%5,%6,%7}, {%8,%9}, {%0,%1,%2,%3};"
        : "+f"(c[0]), "+f"(c[1]), "+f"(c[2]), "+f"(c[3])
        : "r"(a[0]), "r"(a[1]), "r"(a[2]), "r"(a[3]), "r"(b[0]), "r"(b[1]));
}

__device__ __forceinline__ uint32_t pack_f16(float a, float b) {
    __half2 t = __floats2half2_rn(a, b);
    return *(uint32_t*)&t;
}

__device__ __forceinline__ void cp16(uint32_t dst, const void* src) {
    asm volatile("cp.async.cg.shared.global [%0], [%1], 16;" :: "r"(dst), "l"(src));
}
#define CP_COMMIT() asm volatile("cp.async.commit_group;" ::: "memory")
#define CP_WAIT1()  asm volatile("cp.async.wait_group 1;" ::: "memory")
#define CP_WAIT3()  asm volatile("cp.async.wait_group 3;" ::: "memory")
#define CP_WAIT0()  asm volatile("cp.async.wait_group 0;" ::: "memory")

// ---------------------------------------------------------------------------
// fused fp32 -> fp16 conversion (hi only)
// ---------------------------------------------------------------------------
#define N4X (BATCH * SEQ * DIM / 4)      // 1048576
#define N4W (3 * DIM * DIM / 4)          // 786432
#define N4O (DIM * DIM / 4)              // 262144

__global__ void cvt_all(const float4* __restrict__ x,
                        const float4* __restrict__ w_in,
                        const float4* __restrict__ w_out,
                        uint2* __restrict__ xh, uint2* __restrict__ wih,
                        uint2* __restrict__ woh)
{
    int i = blockIdx.x * blockDim.x + threadIdx.x;
    if (i < N4X) {
        float4 f = x[i];
        xh[i] = make_uint2(pack_f16(f.x, f.y), pack_f16(f.z, f.w));
    }
    if (i < N4W) {
        float4 f = w_in[i];
        wih[i] = make_uint2(pack_f16(f.x, f.y), pack_f16(f.z, f.w));
    }
    if (i < N4O) {
        float4 f = w_out[i];
        woh[i] = make_uint2(pack_f16(f.x, f.y), pack_f16(f.z, f.w));
    }
}

// ---------------------------------------------------------------------------
// GEMM: 128x128 tile, pure fp16 (C = Ah*Bh + bias), 256 threads, 2 CTAs/SM.
// BK=32, 5-stage cp.async ring, wait_group 3 (4 stages in flight).
// Stage = [Ah | Bh], rows padded to 80B. 5 stages = 102400 B.
// OUTHALF=1: fp16 out, columns < qcols scaled 0.125. OUTHALF=0: fp32 out.
// ---------------------------------------------------------------------------
#define GTILE 10240
#define GSTG  (2 * GTILE)
#define NSTG  5
#define GEMM_SMEM (NSTG * GSTG)     // 102400

template <int OUTHALF>
__global__ __launch_bounds__(256, 2)
void gemm_k(int M, int N, int K,
            const f16* __restrict__ Ah, const f16* __restrict__ Bh,
            const float* __restrict__ bias, int qcols,
            float* __restrict__ C, f16* __restrict__ Ch)
{
    extern __shared__ char smem[];
    const uint32_t sb = smem_u32(smem);
    const int tid = threadIdx.x, wid = tid >> 5, lane = tid & 31;
    const int bx = blockIdx.x, by = blockIdx.y;
    const int warpM = wid & 1, warpN = wid >> 1;

    const int r = tid >> 1;
    const int cb = (tid & 1) * 2;
    const f16* pAh = Ah + (size_t)(by * 128 + r) * K;
    const f16* pBh = Bh + (size_t)(bx * 128 + r) * K;
    const uint32_t sdst = sb + (uint32_t)(r * 80 + cb * 16);

    float acc[4][4][4];
#pragma unroll
    for (int i = 0; i < 4; i++)
#pragma unroll
        for (int j = 0; j < 4; j++)
#pragma unroll
            for (int v = 0; v < 4; v++) acc[i][j][v] = 0.f;

    const int KC = K >> 5;   // 32 chunks (K=1024)

    auto issue = [&](int kt, int s) {
        const int k0 = kt * 32 + cb * 8;
        const uint32_t d = sdst + (uint32_t)(s * GSTG);
        cp16(d,              pAh + k0);
        cp16(d + 16,         pAh + k0 + 8);
        cp16(d + GTILE,      pBh + k0);
        cp16(d + GTILE + 16, pBh + k0 + 8);
        CP_COMMIT();
    };

    // prologue: fill 4 stages
    issue(0, 0);
    issue(1, 1);
    issue(2, 2);
    issue(3, 3);

    const int aRow = warpM * 64 + ((lane >> 3) & 1) * 8 + (lane & 7);
    const int aColHalf = (lane >> 4) * 16;
    const int bRow = warpN * 32 + (lane >> 4) * 8 + (lane & 7);
    const int bColHalf = ((lane >> 3) & 1) * 16;

    for (int kt = 0; kt < KC; kt++) {
        CP_WAIT3();
        __syncthreads();
        if (kt + 4 < KC) issue(kt + 4, (kt + 4) % NSTG);
        else             CP_COMMIT();

        const uint32_t sAh = sb + (uint32_t)((kt % NSTG) * GSTG);
        const uint32_t sBh = sAh + GTILE;

#pragma unroll
        for (int ks = 0; ks < 2; ks++) {
            uint32_t ah[4][4], bh[4][2];
            const uint32_t acol = (uint32_t)(ks * 32 + aColHalf);
            const uint32_t bcol = (uint32_t)(ks * 32 + bColHalf);
#pragma unroll
            for (int mt = 0; mt < 4; mt++) {
                uint32_t off = (uint32_t)((aRow + mt * 16) * 80) + acol;
                ldmatrix_x4(ah[mt], sAh + off);
            }
#pragma unroll
            for (int pr = 0; pr < 2; pr++) {
                uint32_t off = (uint32_t)((bRow + pr * 16) * 80) + bcol;
                uint32_t r0[4];
                ldmatrix_x4(r0, sBh + off);
                bh[pr * 2 + 0][0] = r0[0]; bh[pr * 2 + 0][1] = r0[1];
                bh[pr * 2 + 1][0] = r0[2]; bh[pr * 2 + 1][1] = r0[3];
            }
#pragma unroll
            for (int mt = 0; mt < 4; mt++)
#pragma unroll
                for (int nt = 0; nt < 4; nt++)
                    mma_f16(acc[mt][nt], ah[mt], bh[nt]);
        }
    }

    const int crow = by * 128 + warpM * 64 + (lane >> 2);
    const int ccol = bx * 128 + warpN * 32 + (lane & 3) * 2;
#pragma unroll
    for (int nt = 0; nt < 4; nt++) {
        const int col = ccol + nt * 8;
        const float s = (OUTHALF && col < qcols) ? 0.125f : 1.0f;
        const float b0 = bias[col], b1 = bias[col + 1];
#pragma unroll
        for (int mt = 0; mt < 4; mt++) {
            const int r0 = crow + mt * 16;
            const float v00 = (acc[mt][nt][0] + b0) * s, v01 = (acc[mt][nt][1] + b1) * s;
            const float v10 = (acc[mt][nt][2] + b0) * s, v11 = (acc[mt][nt][3] + b1) * s;
            if (OUTHALF) {
                *(uint32_t*)(Ch + (size_t)r0 * N + col)       = pack_f16(v00, v01);
                *(uint32_t*)(Ch + (size_t)(r0 + 8) * N + col) = pack_f16(v10, v11);
            } else {
                *(float2*)(C + (size_t)r0 * N + col)       = make_float2(v00, v01);
                *(float2*)(C + (size_t)(r0 + 8) * N + col) = make_float2(v10, v11);
            }
        }
    }
}

// ---------------------------------------------------------------------------
// Flash attention, pure fp16, causal, WORK-PAIRED: CTA bi handles q-tiles
// {bi, NQT-1-bi} -> constant 34 KV-tile loads per CTA -> one uniform wave.
// Grid: (NQT/2, B*H), 256 threads, 2 CTAs/SM. 3-stage cp.async.
// Stage (18432B) = [Kh 9216 | Vh 9216], rows padded to 144B.
// ---------------------------------------------------------------------------
#define ASTR 144
#define KV_T 9216
#define STG_A 18432
#define ATT_SMEM (3 * STG_A)       // 55296

__global__ __launch_bounds__(256, 2)
void attn_mma(const f16* __restrict__ qkvh, f16* __restrict__ oh,
              const int* __restrict__ maskp)
{
    extern __shared__ char sm[];
    const uint32_t sb = smem_u32(sm);
    const int tid = threadIdx.x, wid = tid >> 5, lane = tid & 31;
    const int bi = blockIdx.x;
    const int bh = blockIdx.y;
    const int b = bh >> 4, h = bh & 15;
    const int mask = maskp[0];

    // constant per-thread addressing
    const int tt = tid & 127;
    const int kr = tt >> 1, kc0 = (tt & 1) * 4;
    const size_t kvcol = h * 64 + (tid < 128 ? DIM : 2 * DIM) + kc0 * 8;
    const uint32_t kvdst = (uint32_t)((tid < 128 ? 0 : KV_T) + kr * ASTR + kc0 * 16);
    const uint32_t koff = (uint32_t)(
        (((lane >> 4) << 3) + (lane & 7)) * ASTR + (((lane >> 3) & 1) * 8) * 2);
    const uint32_t voff = (uint32_t)(KV_T +
        ((((lane >> 3) & 1) * 8 + (lane & 7)) * ASTR) + (((lane >> 4) & 1) * 8) * 2);

#pragma unroll 1
    for (int p = 0; p < 2; p++) {
        const int qt = p ? (NQT - 1 - bi) : bi;
        const int q0 = qt * 128;

        // ---- stage Qh via cp.async, consume into registers ----
        {
            const int r = tid >> 1, c0 = (tid & 1) * 4;
            const size_t grow = ((size_t)(b * SEQ + q0 + r)) * (3 * DIM) + h * 64 + c0 * 8;
            const uint32_t dh = sb + (uint32_t)(r * ASTR + c0 * 16);
#pragma unroll
            for (int j = 0; j < 4; j++)
                cp16(dh + j * 16, qkvh + grow + j * 8);
            CP_COMMIT();
            CP_WAIT0();
            __syncthreads();
        }

        uint32_t qh[4][4];
#pragma unroll
        for (int j = 0; j < 4; j++) {
            uint32_t addr = sb + (uint32_t)((wid * 16 + (lane & 15)) * ASTR
                           + (j * 16 + ((lane >> 4) & 1) * 8) * 2);
            ldmatrix_x4(qh[j], addr);
        }
        __syncthreads();

        float o[8][4];
#pragma unroll
        for (int t = 0; t < 8; t++)
#pragma unroll
            for (int v = 0; v < 4; v++) o[t][v] = 0.f;
        float m0 = -1e30f, m1 = -1e30f, l0 = 0.f, l1 = 0.f;

        const int nkt_load = mask ? (2 * qt + 2) : (SEQ / 64);
        const int nkt_w    = mask ? (2 * qt + 1 + (wid >= 4 ? 1 : 0)) : (SEQ / 64);

        auto issueKV = [&](int kt, int s) {
            const size_t grow = ((size_t)(b * SEQ + kt * 64 + kr)) * (3 * DIM) + kvcol;
            const uint32_t d = sb + (uint32_t)(s * STG_A) + kvdst;
#pragma unroll
            for (int j = 0; j < 4; j++)
                cp16(d + j * 16, qkvh + grow + j * 8);
            CP_COMMIT();
        };

        issueKV(0, 0);
        if (nkt_load > 1) issueKV(1, 1); else CP_COMMIT();

        for (int kt = 0; kt < nkt_load; kt++) {
            CP_WAIT1();
            __syncthreads();
            if (kt + 2 < nkt_load) issueKV(kt + 2, (kt + 2) % 3);
            else                   CP_COMMIT();
            if (kt >= nkt_w) continue;

            const uint32_t stg = sb + (uint32_t)((kt % 3) * STG_A);
            const uint32_t kfrag = stg + koff;
            const uint32_t vfrag = stg + voff;

            // ---- scores = Qs * Kh ----
            float sc[8][4];
#pragma unroll
            for (int t = 0; t < 8; t++)
#pragma unroll
                for (int v = 0; v < 4; v++) sc[t][v] = 0.f;

#pragma unroll
            for (int j = 0; j < 4; j++) {
#pragma unroll
                for (int t = 0; t < 4; t++) {
                    uint32_t addr = kfrag + (uint32_t)(t * 16 * ASTR + j * 32);
                    uint32_t rh[4];
                    ldmatrix_x4(rh, addr);
                    mma_f16(sc[2 * t + 0], qh[j], rh);
                    mma_f16(sc[2 * t + 1], qh[j], rh + 2);
                }
            }

            // ---- online softmax ----
            const int row0 = q0 + wid * 16 + (lane >> 2);
            const int row1 = row0 + 8;
            const int cbase = kt * 64 + (lane & 3) * 2;
            const bool needmask = mask && (kt * 64 + 63 > q0 + wid * 16);
            if (needmask) {
#pragma unroll
                for (int t = 0; t < 8; t++) {
                    int c0 = cbase + t * 8, c1 = c0 + 1;
                    if (c0 > row0) sc[t][0] = -1e30f;
                    if (c1 > row0) sc[t][1] = -1e30f;
                    if (c0 > row1) sc[t][2] = -1e30f;
                    if (c1 > row1) sc[t][3] = -1e30f;
                }
            }
            float mt0 = -1e30f, mt1 = -1e30f;
#pragma unroll
            for (int t = 0; t < 8; t++) {
                mt0 = fmaxf(mt0, fmaxf(sc[t][0], sc[t][1]));
                mt1 = fmaxf(mt1, fmaxf(sc[t][2], sc[t][3]));
            }
            mt0 = fmaxf(mt0, __shfl_xor_sync(0xffffffffu, mt0, 1));
            mt0 = fmaxf(mt0, __shfl_xor_sync(0xffffffffu, mt0, 2));
            mt1 = fmaxf(mt1, __shfl_xor_sync(0xffffffffu, mt1, 1));
            mt1 = fmaxf(mt1, __shfl_xor_sync(0xffffffffu, mt1, 2));
            const float mn0 = fmaxf(m0, mt0), mn1 = fmaxf(m1, mt1);
            const float a0 = __expf(m0 - mn0), a1 = __expf(m1 - mn1);

            uint32_t ph[8][2];
            float s0 = 0.f, s1 = 0.f;
#pragma unroll
            for (int t = 0; t < 8; t++) {
                float p00 = __expf(sc[t][0] - mn0);
                float p01 = __expf(sc[t][1] - mn0);
                float p10 = __expf(sc[t][2] - mn1);
                float p11 = __expf(sc[t][3] - mn1);
                s0 += p00 + p01;
                s1 += p10 + p11;
                ph[t][0] = pack_f16(p00, p01);
                ph[t][1] = pack_f16(p10, p11);
            }
            s0 += __shfl_xor_sync(0xffffffffu, s0, 1);
            s0 += __shfl_xor_sync(0xffffffffu, s0, 2);
            s1 += __shfl_xor_sync(0xffffffffu, s1, 1);
            s1 += __shfl_xor_sync(0xffffffffu, s1, 2);
            m0 = mn0; m1 = mn1;
            l0 = l0 * a0 + s0;
            l1 = l1 * a1 + s1;
#pragma unroll
            for (int t = 0; t < 8; t++) {
                o[t][0] *= a0; o[t][1] *= a0;
                o[t][2] *= a1; o[t][3] *= a1;
            }

            // ---- O += Ph * Vh ----
#pragma unroll
            for (int j = 0; j < 4; j++) {
                uint32_t afh[4] = { ph[2*j][0], ph[2*j][1], ph[2*j+1][0], ph[2*j+1][1] };
#pragma unroll
                for (int t = 0; t < 4; t++) {
                    uint32_t addr = vfrag + (uint32_t)(j * 16 * ASTR + t * 32);
                    uint32_t rh[4];
                    ldmatrix_x4_trans(rh, addr);
                    mma_f16(o[2 * t + 0], afh, rh);
                    mma_f16(o[2 * t + 1], afh, rh + 2);
                }
            }
        }

        // ---- write O (fp16 — feeds proj as A operand) ----
        const float il0 = 1.0f / l0, il1 = 1.0f / l1;
        const int orow = q0 + wid * 16 + (lane >> 2);
        const size_t obase = ((size_t)b * SEQ + orow) * DIM + h * 64 + (lane & 3) * 2;
#pragma unroll
        for (int t = 0; t < 8; t++) {
            *(uint32_t*)(oh + obase + t * 8)           = pack_f16(o[t][0] * il0, o[t][1] * il0);
            *(uint32_t*)(oh + obase + 8 * DIM + t * 8) = pack_f16(o[t][2] * il1, o[t][3] * il1);
        }

        // drain outstanding cp.async before reusing smem for next sub-tile
        CP_WAIT0();
        __syncthreads();
    }
}

// ---------------------------------------------------------------------------
// Launch
// ---------------------------------------------------------------------------
extern "C" void kernel_launch(void* const* d_in, const int* in_sizes, int n_in,
                              void* d_out, int out_size)
{
    const float* x     = (const float*)d_in[0];
    const float* w_in  = (const float*)d_in[1];
    const float* b_in  = (const float*)d_in[2];
    const float* w_out = (const float*)d_in[3];
    const float* b_out = (const float*)d_in[4];
    const int*   mask  = (const int*)d_in[5];
    float* out = (float*)d_out;

    f16 *xh, *wih, *woh, *qkvh, *ah;
    cudaGetSymbolAddress((void**)&xh,  g_xh);
    cudaGetSymbolAddress((void**)&wih, g_wih);
    cudaGetSymbolAddress((void**)&woh, g_woh);
    cudaGetSymbolAddress((void**)&qkvh, g_qkvh);
    cudaGetSymbolAddress((void**)&ah,  g_ah);

    const int M = BATCH * SEQ;      // 4096
    const int K = DIM;              // 1024
    const int N1 = 3 * DIM;         // 3072
    const int N2 = DIM;             // 1024

    cudaFuncSetAttribute((const void*)gemm_k<1>, cudaFuncAttributeMaxDynamicSharedMemorySize, GEMM_SMEM);
    cudaFuncSetAttribute((const void*)gemm_k<0>, cudaFuncAttributeMaxDynamicSharedMemorySize, GEMM_SMEM);
    cudaFuncSetAttribute(attn_mma, cudaFuncAttributeMaxDynamicSharedMemorySize, ATT_SMEM);

    // 0) fused conversion (x, w_in, w_out -> fp16)
    cvt_all<<<(N4X + 255) / 256, 256>>>((const float4*)x, (const float4*)w_in,
                                        (const float4*)w_out,
                                        (uint2*)xh, (uint2*)wih, (uint2*)woh);
    // 1) QKV projection (pure fp16, 5-stage pipeline) -> fp16, Q pre-scaled
    {
        dim3 grid(N1 / 128, M / 128);
        gemm_k<1><<<grid, 256, GEMM_SMEM>>>(M, N1, K, xh, wih, b_in, DIM,
                                            nullptr, qkvh);
    }
    // 2) causal attention (work-paired) -> fp16
    {
        dim3 grid(NQT / 2, BATCH * HEADS);
        attn_mma<<<grid, 256, ATT_SMEM>>>(qkvh, ah, mask);
    }
    // 3) output projection (pure fp16, 5-stage pipeline) -> fp32 out
    {
        dim3 grid(N2 / 128, M / 128);
        gemm_k<0><<<grid, 256, GEMM_SMEM>>>(M, N2, K, ah, woh, b_out, 0,
                                            out, nullptr);
    }
}

// round 15
// speedup vs baseline: 1.0751x; 1.0102x over previous
#include <cuda_runtime.h>
#include <cuda_fp16.h>
#include <cstdint>

// Problem constants
#define BATCH 2
#define SEQ   2048
#define DIM   1024
#define HEADS 16
#define DHEAD 64
#define NQT   (SEQ / 128)          // 16 q-tiles

typedef __half f16;

// Scratch (device globals — no allocations allowed)
__device__ f16 g_xh [(size_t)BATCH * SEQ * DIM];
__device__ f16 g_wih[(size_t)3 * DIM * DIM];
__device__ f16 g_woh[(size_t)DIM * DIM];
__device__ f16 g_qkvh[(size_t)BATCH * SEQ * 3 * DIM];
__device__ f16 g_ah [(size_t)BATCH * SEQ * DIM];

// ---------------------------------------------------------------------------
// helpers
// ---------------------------------------------------------------------------
__device__ __forceinline__ uint32_t smem_u32(const void* p) {
    uint32_t a;
    asm("{ .reg .u64 t; cvta.to.shared.u64 t, %1; cvt.u32.u64 %0, t; }" : "=r"(a) : "l"(p));
    return a;
}

__device__ __forceinline__ void ldmatrix_x4(uint32_t* r, uint32_t addr) {
    asm volatile("ldmatrix.sync.aligned.m8n8.x4.shared.b16 {%0,%1,%2,%3}, [%4];"
                 : "=r"(r[0]), "=r"(r[1]), "=r"(r[2]), "=r"(r[3]) : "r"(addr));
}

__device__ __forceinline__ void ldmatrix_x4_trans(uint32_t* r, uint32_t addr) {
    asm volatile("ldmatrix.sync.aligned.m8n8.x4.trans.shared.b16 {%0,%1,%2,%3}, [%4];"
                 : "=r"(r[0]), "=r"(r[1]), "=r"(r[2]), "=r"(r[3]) : "r"(addr));
}

__device__ __forceinline__ void mma_f16(float* c, const uint32_t* a, const uint32_t* b) {
    asm volatile(
        "mma.sync.aligned.m16n8k16.row.col.f32.f16.f16.f32 "
        "{%0,%1,%2,%3}, {%4,%5,%6,%7}, {%8,%9}, {%0,%1,%2,%3};"
        : "+f"(c[0]), "+f"(c[1]), "+f"(c[2]), "+f"(c[3])
        : "r"(a[0]), "r"(a[1]), "r"(a[2]), "r"(a[3]), "r"(b[0]), "r"(b[1]));
}

__device__ __forceinline__ uint32_t pack_f16(float a, float b) {
    __half2 t = __floats2half2_rn(a, b);
    return *(uint32_t*)&t;
}

__device__ __forceinline__ void cp16(uint32_t dst, const void* src) {
    asm volatile("cp.async.cg.shared.global [%0], [%1], 16;" :: "r"(dst), "l"(src));
}
#define CP_COMMIT() asm volatile("cp.async.commit_group;" ::: "memory")
#define CP_WAIT1()  asm volatile("cp.async.wait_group 1;" ::: "memory")
#define CP_WAIT0()  asm volatile("cp.async.wait_group 0;" ::: "memory")

// ---------------------------------------------------------------------------
// fused fp32 -> fp16 conversion (hi only)
// ---------------------------------------------------------------------------
#define N4X (BATCH * SEQ * DIM / 4)      // 1048576
#define N4W (3 * DIM * DIM / 4)          // 786432
#define N4O (DIM * DIM / 4)              // 262144

__global__ void cvt_all(const float4* __restrict__ x,
                        const float4* __restrict__ w_in,
                        const float4* __restrict__ w_out,
                        uint2* __restrict__ xh, uint2* __restrict__ wih,
                        uint2* __restrict__ woh)
{
    int i = blockIdx.x * blockDim.x + threadIdx.x;
    if (i < N4X) {
        float4 f = x[i];
        xh[i] = make_uint2(pack_f16(f.x, f.y), pack_f16(f.z, f.w));
    }
    if (i < N4W) {
        float4 f = w_in[i];
        wih[i] = make_uint2(pack_f16(f.x, f.y), pack_f16(f.z, f.w));
    }
    if (i < N4O) {
        float4 f = w_out[i];
        woh[i] = make_uint2(pack_f16(f.x, f.y), pack_f16(f.z, f.w));
    }
}

// ---------------------------------------------------------------------------
// GEMM: 128x128 tile, pure fp16 (C = Ah*Bh + bias), 256 threads, 2 CTAs/SM.
// BK=32, 3-stage cp.async ring (R12 proven config).
// Stage = [Ah | Bh], rows padded to 80B. 3 stages = 61440 B.
// OUTHALF=1: fp16 out, columns < qcols scaled 0.125. OUTHALF=0: fp32 out.
// ---------------------------------------------------------------------------
#define GTILE 10240
#define GSTG  (2 * GTILE)
#define GEMM_SMEM (3 * GSTG)     // 61440

template <int OUTHALF>
__global__ __launch_bounds__(256, 2)
void gemm_k(int M, int N, int K,
            const f16* __restrict__ Ah, const f16* __restrict__ Bh,
            const float* __restrict__ bias, int qcols,
            float* __restrict__ C, f16* __restrict__ Ch)
{
    extern __shared__ char smem[];
    const uint32_t sb = smem_u32(smem);
    const int tid = threadIdx.x, wid = tid >> 5, lane = tid & 31;
    const int bx = blockIdx.x, by = blockIdx.y;
    const int warpM = wid & 1, warpN = wid >> 1;

    const int r = tid >> 1;
    const int cb = (tid & 1) * 2;
    const f16* pAh = Ah + (size_t)(by * 128 + r) * K;
    const f16* pBh = Bh + (size_t)(bx * 128 + r) * K;
    const uint32_t sdst = sb + (uint32_t)(r * 80 + cb * 16);

    float acc[4][4][4];
#pragma unroll
    for (int i = 0; i < 4; i++)
#pragma unroll
        for (int j = 0; j < 4; j++)
#pragma unroll
            for (int v = 0; v < 4; v++) acc[i][j][v] = 0.f;

    const int KC = K >> 5;   // 32 chunks

    auto issue = [&](int kt, int s) {
        const int k0 = kt * 32 + cb * 8;
        const uint32_t d = sdst + (uint32_t)(s * GSTG);
        cp16(d,              pAh + k0);
        cp16(d + 16,         pAh + k0 + 8);
        cp16(d + GTILE,      pBh + k0);
        cp16(d + GTILE + 16, pBh + k0 + 8);
        CP_COMMIT();
    };

    issue(0, 0);
    issue(1, 1);

    const int aRow = warpM * 64 + ((lane >> 3) & 1) * 8 + (lane & 7);
    const int aColHalf = (lane >> 4) * 16;
    const int bRow = warpN * 32 + (lane >> 4) * 8 + (lane & 7);
    const int bColHalf = ((lane >> 3) & 1) * 16;

    for (int kt = 0; kt < KC; kt++) {
        CP_WAIT1();
        __syncthreads();
        if (kt + 2 < KC) issue(kt + 2, (kt + 2) % 3);
        else             CP_COMMIT();

        const uint32_t sAh = sb + (uint32_t)((kt % 3) * GSTG);
        const uint32_t sBh = sAh + GTILE;

#pragma unroll
        for (int ks = 0; ks < 2; ks++) {
            uint32_t ah[4][4], bh[4][2];
            const uint32_t acol = (uint32_t)(ks * 32 + aColHalf);
            const uint32_t bcol = (uint32_t)(ks * 32 + bColHalf);
#pragma unroll
            for (int mt = 0; mt < 4; mt++) {
                uint32_t off = (uint32_t)((aRow + mt * 16) * 80) + acol;
                ldmatrix_x4(ah[mt], sAh + off);
            }
#pragma unroll
            for (int pr = 0; pr < 2; pr++) {
                uint32_t off = (uint32_t)((bRow + pr * 16) * 80) + bcol;
                uint32_t r0[4];
                ldmatrix_x4(r0, sBh + off);
                bh[pr * 2 + 0][0] = r0[0]; bh[pr * 2 + 0][1] = r0[1];
                bh[pr * 2 + 1][0] = r0[2]; bh[pr * 2 + 1][1] = r0[3];
            }
#pragma unroll
            for (int mt = 0; mt < 4; mt++)
#pragma unroll
                for (int nt = 0; nt < 4; nt++)
                    mma_f16(acc[mt][nt], ah[mt], bh[nt]);
        }
    }

    const int crow = by * 128 + warpM * 64 + (lane >> 2);
    const int ccol = bx * 128 + warpN * 32 + (lane & 3) * 2;
#pragma unroll
    for (int nt = 0; nt < 4; nt++) {
        const int col = ccol + nt * 8;
        const float s = (OUTHALF && col < qcols) ? 0.125f : 1.0f;
        const float b0 = bias[col], b1 = bias[col + 1];
#pragma unroll
        for (int mt = 0; mt < 4; mt++) {
            const int r0 = crow + mt * 16;
            const float v00 = (acc[mt][nt][0] + b0) * s, v01 = (acc[mt][nt][1] + b1) * s;
            const float v10 = (acc[mt][nt][2] + b0) * s, v11 = (acc[mt][nt][3] + b1) * s;
            if (OUTHALF) {
                *(uint32_t*)(Ch + (size_t)r0 * N + col)       = pack_f16(v00, v01);
                *(uint32_t*)(Ch + (size_t)(r0 + 8) * N + col) = pack_f16(v10, v11);
            } else {
                *(float2*)(C + (size_t)r0 * N + col)       = make_float2(v00, v01);
                *(float2*)(C + (size_t)(r0 + 8) * N + col) = make_float2(v10, v11);
            }
        }
    }
}

// ---------------------------------------------------------------------------
// Flash attention, pure fp16, causal, WORK-PAIRED: CTA bi handles q-tiles
// {bi, NQT-1-bi} -> constant 34 KV-tile loads per CTA -> one uniform wave.
// Grid: (NQT/2, B*H), 256 threads, 2 CTAs/SM. 3-stage KV ring + SEPARATE
// Q region (no aliasing -> no end-of-subtile drain).
// smem = 3*18432 (KV) + 18432 (Q) = 73728 B.
// ---------------------------------------------------------------------------
#define ASTR 144
#define KV_T 9216
#define STG_A 18432
#define Q_OFF (3 * STG_A)
#define ATT_SMEM (4 * STG_A)       // 73728

__global__ __launch_bounds__(256, 2)
void attn_mma(const f16* __restrict__ qkvh, f16* __restrict__ oh,
              const int* __restrict__ maskp)
{
    extern __shared__ char sm[];
    const uint32_t sb = smem_u32(sm);
    const int tid = threadIdx.x, wid = tid >> 5, lane = tid & 31;
    const int bi = blockIdx.x;
    const int bh = blockIdx.y;
    const int b = bh >> 4, h = bh & 15;
    const int mask = maskp[0];

    // constant per-thread addressing
    const int tt = tid & 127;
    const int kr = tt >> 1, kc0 = (tt & 1) * 4;
    const size_t kvcol = h * 64 + (tid < 128 ? DIM : 2 * DIM) + kc0 * 8;
    const uint32_t kvdst = (uint32_t)((tid < 128 ? 0 : KV_T) + kr * ASTR + kc0 * 16);
    const uint32_t koff = (uint32_t)(
        (((lane >> 4) << 3) + (lane & 7)) * ASTR + (((lane >> 3) & 1) * 8) * 2);
    const uint32_t voff = (uint32_t)(KV_T +
        ((((lane >> 3) & 1) * 8 + (lane & 7)) * ASTR) + (((lane >> 4) & 1) * 8) * 2);

#pragma unroll 1
    for (int p = 0; p < 2; p++) {
        const int qt = p ? (NQT - 1 - bi) : bi;
        const int q0 = qt * 128;

        // ---- stage Qh into its own region, consume into registers ----
        {
            const int r = tid >> 1, c0 = (tid & 1) * 4;
            const size_t grow = ((size_t)(b * SEQ + q0 + r)) * (3 * DIM) + h * 64 + c0 * 8;
            const uint32_t dh = sb + Q_OFF + (uint32_t)(r * ASTR + c0 * 16);
#pragma unroll
            for (int j = 0; j < 4; j++)
                cp16(dh + j * 16, qkvh + grow + j * 8);
            CP_COMMIT();
            CP_WAIT0();
            __syncthreads();
        }

        uint32_t qh[4][4];
#pragma unroll
        for (int j = 0; j < 4; j++) {
            uint32_t addr = sb + Q_OFF + (uint32_t)((wid * 16 + (lane & 15)) * ASTR
                           + (j * 16 + ((lane >> 4) & 1) * 8) * 2);
            ldmatrix_x4(qh[j], addr);
        }
        __syncthreads();

        float o[8][4];
#pragma unroll
        for (int t = 0; t < 8; t++)
#pragma unroll
            for (int v = 0; v < 4; v++) o[t][v] = 0.f;
        float m0 = -1e30f, m1 = -1e30f, l0 = 0.f, l1 = 0.f;

        const int nkt_load = mask ? (2 * qt + 2) : (SEQ / 64);
        const int nkt_w    = mask ? (2 * qt + 1 + (wid >= 4 ? 1 : 0)) : (SEQ / 64);

        auto issueKV = [&](int kt, int s) {
            const size_t grow = ((size_t)(b * SEQ + kt * 64 + kr)) * (3 * DIM) + kvcol;
            const uint32_t d = sb + (uint32_t)(s * STG_A) + kvdst;
#pragma unroll
            for (int j = 0; j < 4; j++)
                cp16(d + j * 16, qkvh + grow + j * 8);
            CP_COMMIT();
        };

        issueKV(0, 0);
        if (nkt_load > 1) issueKV(1, 1); else CP_COMMIT();

        for (int kt = 0; kt < nkt_load; kt++) {
            CP_WAIT1();
            __syncthreads();
            if (kt + 2 < nkt_load) issueKV(kt + 2, (kt + 2) % 3);
            else                   CP_COMMIT();
            if (kt >= nkt_w) continue;

            const uint32_t stg = sb + (uint32_t)((kt % 3) * STG_A);
            const uint32_t kfrag = stg + koff;
            const uint32_t vfrag = stg + voff;

            // ---- scores = Qs * Kh ----
            float sc[8][4];
#pragma unroll
            for (int t = 0; t < 8; t++)
#pragma unroll
                for (int v = 0; v < 4; v++) sc[t][v] = 0.f;

#pragma unroll
            for (int j = 0; j < 4; j++) {
#pragma unroll
                for (int t = 0; t < 4; t++) {
                    uint32_t addr = kfrag + (uint32_t)(t * 16 * ASTR + j * 32);
                    uint32_t rh[4];
                    ldmatrix_x4(rh, addr);
                    mma_f16(sc[2 * t + 0], qh[j], rh);
                    mma_f16(sc[2 * t + 1], qh[j], rh + 2);
                }
            }

            // ---- online softmax ----
            const int row0 = q0 + wid * 16 + (lane >> 2);
            const int row1 = row0 + 8;
            const int cbase = kt * 64 + (lane & 3) * 2;
            const bool needmask = mask && (kt * 64 + 63 > q0 + wid * 16);
            if (needmask) {
#pragma unroll
                for (int t = 0; t < 8; t++) {
                    int c0 = cbase + t * 8, c1 = c0 + 1;
                    if (c0 > row0) sc[t][0] = -1e30f;
                    if (c1 > row0) sc[t][1] = -1e30f;
                    if (c0 > row1) sc[t][2] = -1e30f;
                    if (c1 > row1) sc[t][3] = -1e30f;
                }
            }
            float mt0 = -1e30f, mt1 = -1e30f;
#pragma unroll
            for (int t = 0; t < 8; t++) {
                mt0 = fmaxf(mt0, fmaxf(sc[t][0], sc[t][1]));
                mt1 = fmaxf(mt1, fmaxf(sc[t][2], sc[t][3]));
            }
            mt0 = fmaxf(mt0, __shfl_xor_sync(0xffffffffu, mt0, 1));
            mt0 = fmaxf(mt0, __shfl_xor_sync(0xffffffffu, mt0, 2));
            mt1 = fmaxf(mt1, __shfl_xor_sync(0xffffffffu, mt1, 1));
            mt1 = fmaxf(mt1, __shfl_xor_sync(0xffffffffu, mt1, 2));
            const float mn0 = fmaxf(m0, mt0), mn1 = fmaxf(m1, mt1);
            const float a0 = __expf(m0 - mn0), a1 = __expf(m1 - mn1);

            uint32_t ph[8][2];
            float s0 = 0.f, s1 = 0.f;
#pragma unroll
            for (int t = 0; t < 8; t++) {
                float p00 = __expf(sc[t][0] - mn0);
                float p01 = __expf(sc[t][1] - mn0);
                float p10 = __expf(sc[t][2] - mn1);
                float p11 = __expf(sc[t][3] - mn1);
                s0 += p00 + p01;
                s1 += p10 + p11;
                ph[t][0] = pack_f16(p00, p01);
                ph[t][1] = pack_f16(p10, p11);
            }
            s0 += __shfl_xor_sync(0xffffffffu, s0, 1);
            s0 += __shfl_xor_sync(0xffffffffu, s0, 2);
            s1 += __shfl_xor_sync(0xffffffffu, s1, 1);
            s1 += __shfl_xor_sync(0xffffffffu, s1, 2);
            m0 = mn0; m1 = mn1;
            l0 = l0 * a0 + s0;
            l1 = l1 * a1 + s1;
#pragma unroll
            for (int t = 0; t < 8; t++) {
                o[t][0] *= a0; o[t][1] *= a0;
                o[t][2] *= a1; o[t][3] *= a1;
            }

            // ---- O += Ph * Vh ----
#pragma unroll
            for (int j = 0; j < 4; j++) {
                uint32_t afh[4] = { ph[2*j][0], ph[2*j][1], ph[2*j+1][0], ph[2*j+1][1] };
#pragma unroll
                for (int t = 0; t < 4; t++) {
                    uint32_t addr = vfrag + (uint32_t)(j * 16 * ASTR + t * 32);
                    uint32_t rh[4];
                    ldmatrix_x4_trans(rh, addr);
                    mma_f16(o[2 * t + 0], afh, rh);
                    mma_f16(o[2 * t + 1], afh, rh + 2);
                }
            }
        }

        // ---- write O (fp16 — feeds proj as A operand) ----
        const float il0 = 1.0f / l0, il1 = 1.0f / l1;
        const int orow = q0 + wid * 16 + (lane >> 2);
        const size_t obase = ((size_t)b * SEQ + orow) * DIM + h * 64 + (lane & 3) * 2;
#pragma unroll
        for (int t = 0; t < 8; t++) {
            *(uint32_t*)(oh + obase + t * 8)           = pack_f16(o[t][0] * il0, o[t][1] * il0);
            *(uint32_t*)(oh + obase + 8 * DIM + t * 8) = pack_f16(o[t][2] * il1, o[t][3] * il1);
        }
        // No trailing drain needed: Q has its own region; the p=1 Q staging
        // block performs CP_WAIT0 before any KV stage reuse.
    }
}

// ---------------------------------------------------------------------------
// Launch
// ---------------------------------------------------------------------------
extern "C" void kernel_launch(void* const* d_in, const int* in_sizes, int n_in,
                              void* d_out, int out_size)
{
    const float* x     = (const float*)d_in[0];
    const float* w_in  = (const float*)d_in[1];
    const float* b_in  = (const float*)d_in[2];
    const float* w_out = (const float*)d_in[3];
    const float* b_out = (const float*)d_in[4];
    const int*   mask  = (const int*)d_in[5];
    float* out = (float*)d_out;

    f16 *xh, *wih, *woh, *qkvh, *ah;
    cudaGetSymbolAddress((void**)&xh,  g_xh);
    cudaGetSymbolAddress((void**)&wih, g_wih);
    cudaGetSymbolAddress((void**)&woh, g_woh);
    cudaGetSymbolAddress((void**)&qkvh, g_qkvh);
    cudaGetSymbolAddress((void**)&ah,  g_ah);

    const int M = BATCH * SEQ;      // 4096
    const int K = DIM;              // 1024
    const int N1 = 3 * DIM;         // 3072
    const int N2 = DIM;             // 1024

    cudaFuncSetAttribute((const void*)gemm_k<1>, cudaFuncAttributeMaxDynamicSharedMemorySize, GEMM_SMEM);
    cudaFuncSetAttribute((const void*)gemm_k<0>, cudaFuncAttributeMaxDynamicSharedMemorySize, GEMM_SMEM);
    cudaFuncSetAttribute(attn_mma, cudaFuncAttributeMaxDynamicSharedMemorySize, ATT_SMEM);

    // 0) fused conversion (x, w_in, w_out -> fp16)
    cvt_all<<<(N4X + 255) / 256, 256>>>((const float4*)x, (const float4*)w_in,
                                        (const float4*)w_out,
                                        (uint2*)xh, (uint2*)wih, (uint2*)woh);
    // 1) QKV projection (pure fp16, 3-stage) -> fp16, Q columns pre-scaled 0.125
    {
        dim3 grid(N1 / 128, M / 128);
        gemm_k<1><<<grid, 256, GEMM_SMEM>>>(M, N1, K, xh, wih, b_in, DIM,
                                            nullptr, qkvh);
    }
    // 2) causal attention (work-paired, dedicated Q buffer) -> fp16
    {
        dim3 grid(NQT / 2, BATCH * HEADS);
        attn_mma<<<grid, 256, ATT_SMEM>>>(qkvh, ah, mask);
    }
    // 3) output projection (pure fp16, 3-stage) -> fp32 out
    {
        dim3 grid(N2 / 128, M / 128);
        gemm_k<0><<<grid, 256, GEMM_SMEM>>>(M, N2, K, ah, woh, b_out, 0,
                                            out, nullptr);
    }
}